// round 15
// baseline (speedup 1.0000x reference)
#include <cuda_runtime.h>
#include <cuda_bf16.h>
#include <cuda_fp16.h>
#include <cstdint>

// ---------------------------------------------------------------------------
// MultiScaleDeformableAttention
//   R15: R12 with compile fix (cvt_h2_rn instead of nonexistent
//        __half2_as_uint).
//        (1) parity-aligned DUAL value cache: copyB = image shifted 1 pixel;
//            Phase A picks copy so each sample row read is 128B-aligned.
//        (2) GEMMs double-buffered (1 sync per k-chunk).
// ---------------------------------------------------------------------------

#define BS_       2
#define HEADS_    8
#define LEVELS_   4
#define LEN_V_    18360
#define LEN_Q_    18360
#define MROWS_    (BS_ * LEN_Q_)   // 36720
#define KDIM_     256
#define VH_HALVES (BS_ * HEADS_ * LEN_V_ * 32)      // one copy, in __half
#define VH_BYTES  (VH_HALVES * 2)                   // one copy, in bytes

__device__ __constant__ int c_lh[LEVELS_]    = {96, 48, 24, 12};
__device__ __constant__ int c_lw[LEVELS_]    = {144, 72, 36, 18};
__device__ __constant__ int c_start[LEVELS_] = {0, 13824, 17280, 18144};

// scratch
__device__ __half g_vh [2 * VH_HALVES + 64];   // copyA | copyB(shift -1 pixel)
__device__ float  g_off[BS_ * LEN_Q_ * 256];
__device__ float  g_aw [BS_ * LEN_Q_ * 128 + 2048];
__device__ __half g_xh [MROWS_ * 256];

// fp16 weights [N][K]: slot0 vpk(256), slot1 sok|ak(384), slot2 okern(256)
__device__ __half g_wh [3][384 * KDIM_];
__device__ float  g_biascat[384];

// ---------------------------------------------------------------------------
// helpers
// ---------------------------------------------------------------------------
__device__ __forceinline__ uint32_t cvt_h2_rn(float lo, float hi) {
    uint32_t r;
    asm("cvt.rn.f16x2.f32 %0, %1, %2;" : "=r"(r) : "f"(hi), "f"(lo));
    return r;
}
__device__ __forceinline__ void ldsm4(uint32_t& r0, uint32_t& r1, uint32_t& r2,
                                      uint32_t& r3, uint32_t addr) {
    asm volatile("ldmatrix.sync.aligned.m8n8.x4.shared.b16 {%0,%1,%2,%3}, [%4];"
                 : "=r"(r0), "=r"(r1), "=r"(r2), "=r"(r3) : "r"(addr));
}
__device__ __forceinline__ void mma_f16(float4& d, const uint32_t a[4],
                                        const uint32_t b[2]) {
    asm volatile(
        "mma.sync.aligned.m16n8k16.row.col.f32.f16.f16.f32 "
        "{%0,%1,%2,%3}, {%4,%5,%6,%7}, {%8,%9}, {%0,%1,%2,%3};"
        : "+f"(d.x), "+f"(d.y), "+f"(d.z), "+f"(d.w)
        : "r"(a[0]), "r"(a[1]), "r"(a[2]), "r"(a[3]), "r"(b[0]), "r"(b[1]));
}

// ---------------------------------------------------------------------------
// weight prep (one launch, 4 jobs on blockIdx.y) — all fp16
// ---------------------------------------------------------------------------
__global__ __launch_bounds__(256) void prep_weights_kernel(
    const float* __restrict__ vpk, const float* __restrict__ sok,
    const float* __restrict__ ak,  const float* __restrict__ okern,
    const float* __restrict__ sob, const float* __restrict__ ab)
{
    const int job = blockIdx.y;
    const float* src;
    int N, rowoff, slot;
    switch (job) {
        case 0:  src = vpk;   N = 256; slot = 0; rowoff = 0;   break;
        case 1:  src = sok;   N = 256; slot = 1; rowoff = 0;   break;
        case 2:  src = ak;    N = 128; slot = 1; rowoff = 256; break;
        default: src = okern; N = 256; slot = 2; rowoff = 0;   break;
    }
    int idx = blockIdx.x * 256 + threadIdx.x;
    if (idx < N * 256) {
        int n = idx >> 8;
        int k = idx & 255;
        g_wh[slot][(rowoff + n) * 256 + k] = __float2half_rn(src[k * N + n]);
    }
    if (blockIdx.x == 0) {
        if (job == 1 && threadIdx.x < 256) g_biascat[threadIdx.x] = sob[threadIdx.x];
        if (job == 2 && threadIdx.x < 128) g_biascat[256 + threadIdx.x] = ab[threadIdx.x];
    }
}

// ---------------------------------------------------------------------------
// fp16 GEMM, fp32 A input, double-buffered smem (1 sync / chunk)
// out_mode 0: fp32 dual output    out_mode 1: fp16 head-major value cache x2
// ---------------------------------------------------------------------------
__global__ __launch_bounds__(256) void mma_gemm_f16_kernel(
    const float* __restrict__ A, const __half* __restrict__ W,
    const float* __restrict__ bias,
    float* __restrict__ C0, float* __restrict__ C1,
    int M, int N0, int ld0, int ld1, int out_mode)
{
    __shared__ uint32_t sA[2][128 * 16];
    __shared__ uint32_t sB[2][128 * 16];

    const int tid    = threadIdx.x;
    const int lane   = tid & 31;
    const int wid    = tid >> 5;
    const int warp_m = wid & 1;
    const int warp_n = wid >> 1;
    const int bm     = blockIdx.y * 128;
    const int bn     = blockIdx.x * 128;

    const int lrow  = tid >> 1;
    const int lhalf = tid & 1;
    const int lsw   = (tid >> 2) & 3;
    const bool arow_ok = (bm + lrow) < M;
    const float*  aptr = A + (long)(bm + lrow) * 256 + lhalf * 16;
    const __half* wptr = W + (long)(bn + lrow) * 256 + lhalf * 16;
    const int soff0 = lrow * 16 + (((lhalf * 2 + 0) ^ lsw) << 2);
    const int soff1 = lrow * 16 + (((lhalf * 2 + 1) ^ lsw) << 2);

    const int l16 = lane & 15;
    const int hi4 = lane >> 4;
    const int fsw = (l16 >> 1) & 3;
    const uint32_t bA = (uint32_t)__cvta_generic_to_shared(sA);
    const uint32_t bB = (uint32_t)__cvta_generic_to_shared(sB);
    const uint32_t rA = (uint32_t)(warp_m * 64 + l16) * 64;
    const uint32_t rB = (uint32_t)(warp_n * 32 + l16) * 64;
    uint32_t coff[2];
    coff[0] = (uint32_t)(((0 * 2 + hi4) ^ fsw) * 16);
    coff[1] = (uint32_t)(((1 * 2 + hi4) ^ fsw) * 16);

    float4 acc[4][4];
#pragma unroll
    for (int mi = 0; mi < 4; mi++)
#pragma unroll
        for (int ni = 0; ni < 4; ni++) acc[mi][ni] = make_float4(0.f, 0.f, 0.f, 0.f);

    float4 pa[4];
    uint4  pb[2];

    if (arow_ok) {
        pa[0] = *(const float4*)(aptr + 0);
        pa[1] = *(const float4*)(aptr + 4);
        pa[2] = *(const float4*)(aptr + 8);
        pa[3] = *(const float4*)(aptr + 12);
    } else {
        pa[0] = pa[1] = pa[2] = pa[3] = make_float4(0.f, 0.f, 0.f, 0.f);
    }
    pb[0] = ((const uint4*)wptr)[0];
    pb[1] = ((const uint4*)wptr)[1];

#pragma unroll 1
    for (int k0 = 0; k0 < 8; k0++) {
        const int sel = k0 & 1;
#pragma unroll
        for (int j = 0; j < 2; j++) {
            float4 a0 = pa[2 * j], a1 = pa[2 * j + 1];
            uint4 h;
            h.x = cvt_h2_rn(a0.x, a0.y);
            h.y = cvt_h2_rn(a0.z, a0.w);
            h.z = cvt_h2_rn(a1.x, a1.y);
            h.w = cvt_h2_rn(a1.z, a1.w);
            int off = (j == 0) ? soff0 : soff1;
            *(uint4*)&sA[sel][off] = h;
            *(uint4*)&sB[sel][off] = pb[j];
        }
        __syncthreads();

        if (k0 < 7) {
            const float* ap = aptr + (k0 + 1) * 32;
            if (arow_ok) {
                pa[0] = *(const float4*)(ap + 0);
                pa[1] = *(const float4*)(ap + 4);
                pa[2] = *(const float4*)(ap + 8);
                pa[3] = *(const float4*)(ap + 12);
            }
            const uint4* wp = (const uint4*)(wptr + (k0 + 1) * 32);
            pb[0] = wp[0];
            pb[1] = wp[1];
        }

        const uint32_t sbofs = (uint32_t)(sel * 8192);
#pragma unroll
        for (int ks = 0; ks < 2; ks++) {
            uint32_t a[4][4], b[4][2];
#pragma unroll
            for (int mi = 0; mi < 4; mi++) {
                uint32_t ad = rA + (uint32_t)(mi * 1024) + coff[ks] + sbofs;
                ldsm4(a[mi][0], a[mi][1], a[mi][2], a[mi][3], bA + ad);
            }
#pragma unroll
            for (int nip = 0; nip < 2; nip++) {
                uint32_t bd = rB + (uint32_t)(nip * 1024) + coff[ks] + sbofs;
                uint32_t t0, t1, t2, t3;
                ldsm4(t0, t1, t2, t3, bB + bd);
                b[2 * nip][0] = t0; b[2 * nip + 1][0] = t1;
                b[2 * nip][1] = t2; b[2 * nip + 1][1] = t3;
            }
#pragma unroll
            for (int mi = 0; mi < 4; mi++)
#pragma unroll
                for (int ni = 0; ni < 4; ni++)
                    mma_f16(acc[mi][ni], a[mi], b[ni]);
        }
    }

    const int qrow = lane >> 2;
    const int qk   = lane & 3;
    __half* gvh = (__half*)g_vh;
#pragma unroll
    for (int mi = 0; mi < 4; mi++) {
#pragma unroll
        for (int ni = 0; ni < 4; ni++) {
            int col = bn + warp_n * 32 + ni * 8 + qk * 2;
            float2 bv = *(const float2*)(bias + col);
            int row0 = bm + warp_m * 64 + mi * 16 + qrow;
            int row1 = row0 + 8;
            float2 o0 = make_float2(acc[mi][ni].x + bv.x, acc[mi][ni].y + bv.y);
            float2 o1 = make_float2(acc[mi][ni].z + bv.x, acc[mi][ni].w + bv.y);
            if (out_mode == 1) {
                int h = col >> 5, d = col & 31;
#pragma unroll
                for (int rr = 0; rr < 2; rr++) {
                    int row = rr ? row1 : row0;
                    if (row < M) {
                        int b = row >= LEN_V_;
                        int v = row - b * LEN_V_;
                        long ib = (long)(b * 8 + h) * LEN_V_;
                        float2 ov = rr ? o1 : o0;
                        uint32_t pk = cvt_h2_rn(ov.x, ov.y);
                        *(uint32_t*)(gvh + (ib + v) * 32 + d) = pk;
                        if (v >= 1)
                            *(uint32_t*)(gvh + VH_HALVES + (ib + v - 1) * 32 + d) = pk;
                    }
                }
            } else {
                float* Cp; int ldc, cc;
                if (col < N0) { Cp = C0; ldc = ld0; cc = col; }
                else          { Cp = C1; ldc = ld1; cc = col - N0; }
                if (row0 < M) *(float2*)(Cp + (long)row0 * ldc + cc) = o0;
                if (row1 < M) *(float2*)(Cp + (long)row1 * ldc + cc) = o1;
            }
        }
    }
}

// ---------------------------------------------------------------------------
// fp16 GEMM, fp16 A input (out projection), double-buffered
// ---------------------------------------------------------------------------
__global__ __launch_bounds__(256) void mma_gemm_f16f16_kernel(
    const __half* __restrict__ A, const __half* __restrict__ W,
    const float* __restrict__ bias, float* __restrict__ C, int M, int N)
{
    __shared__ uint32_t sA[2][128 * 16];
    __shared__ uint32_t sB[2][128 * 16];

    const int tid    = threadIdx.x;
    const int lane   = tid & 31;
    const int wid    = tid >> 5;
    const int warp_m = wid & 1;
    const int warp_n = wid >> 1;
    const int bm     = blockIdx.y * 128;
    const int bn     = blockIdx.x * 128;

    const int lrow  = tid >> 1;
    const int lhalf = tid & 1;
    const int lsw   = (tid >> 2) & 3;
    const int arow  = min(bm + lrow, M - 1);
    const __half* aptr = A + (long)arow * 256 + lhalf * 16;
    const __half* wptr = W + (long)(bn + lrow) * 256 + lhalf * 16;
    const int soff0 = lrow * 16 + (((lhalf * 2 + 0) ^ lsw) << 2);
    const int soff1 = lrow * 16 + (((lhalf * 2 + 1) ^ lsw) << 2);

    const int l16 = lane & 15;
    const int hi4 = lane >> 4;
    const int fsw = (l16 >> 1) & 3;
    const uint32_t bA = (uint32_t)__cvta_generic_to_shared(sA);
    const uint32_t bB = (uint32_t)__cvta_generic_to_shared(sB);
    const uint32_t rA = (uint32_t)(warp_m * 64 + l16) * 64;
    const uint32_t rB = (uint32_t)(warp_n * 32 + l16) * 64;
    uint32_t coff[2];
    coff[0] = (uint32_t)(((0 * 2 + hi4) ^ fsw) * 16);
    coff[1] = (uint32_t)(((1 * 2 + hi4) ^ fsw) * 16);

    float4 acc[4][4];
#pragma unroll
    for (int mi = 0; mi < 4; mi++)
#pragma unroll
        for (int ni = 0; ni < 4; ni++) acc[mi][ni] = make_float4(0.f, 0.f, 0.f, 0.f);

    uint4 pa[2], pb[2];
    pa[0] = ((const uint4*)aptr)[0];
    pa[1] = ((const uint4*)aptr)[1];
    pb[0] = ((const uint4*)wptr)[0];
    pb[1] = ((const uint4*)wptr)[1];

#pragma unroll 1
    for (int k0 = 0; k0 < 8; k0++) {
        const int sel = k0 & 1;
        *(uint4*)&sA[sel][soff0] = pa[0];
        *(uint4*)&sA[sel][soff1] = pa[1];
        *(uint4*)&sB[sel][soff0] = pb[0];
        *(uint4*)&sB[sel][soff1] = pb[1];
        __syncthreads();

        if (k0 < 7) {
            const uint4* ap = (const uint4*)(aptr + (k0 + 1) * 32);
            const uint4* wp = (const uint4*)(wptr + (k0 + 1) * 32);
            pa[0] = ap[0]; pa[1] = ap[1];
            pb[0] = wp[0]; pb[1] = wp[1];
        }

        const uint32_t sbofs = (uint32_t)(sel * 8192);
#pragma unroll
        for (int ks = 0; ks < 2; ks++) {
            uint32_t a[4][4], b[4][2];
#pragma unroll
            for (int mi = 0; mi < 4; mi++) {
                uint32_t ad = rA + (uint32_t)(mi * 1024) + coff[ks] + sbofs;
                ldsm4(a[mi][0], a[mi][1], a[mi][2], a[mi][3], bA + ad);
            }
#pragma unroll
            for (int nip = 0; nip < 2; nip++) {
                uint32_t bd = rB + (uint32_t)(nip * 1024) + coff[ks] + sbofs;
                uint32_t t0, t1, t2, t3;
                ldsm4(t0, t1, t2, t3, bB + bd);
                b[2 * nip][0] = t0; b[2 * nip + 1][0] = t1;
                b[2 * nip][1] = t2; b[2 * nip + 1][1] = t3;
            }
#pragma unroll
            for (int mi = 0; mi < 4; mi++)
#pragma unroll
                for (int ni = 0; ni < 4; ni++)
                    mma_f16(acc[mi][ni], a[mi], b[ni]);
        }
    }

    const int qrow = lane >> 2;
    const int qk   = lane & 3;
#pragma unroll
    for (int mi = 0; mi < 4; mi++) {
#pragma unroll
        for (int ni = 0; ni < 4; ni++) {
            int col = bn + warp_n * 32 + ni * 8 + qk * 2;
            float2 bv = *(const float2*)(bias + col);
            int row0 = bm + warp_m * 64 + mi * 16 + qrow;
            int row1 = row0 + 8;
            if (row0 < M)
                *(float2*)(C + (long)row0 * N + col) =
                    make_float2(acc[mi][ni].x + bv.x, acc[mi][ni].y + bv.y);
            if (row1 < M)
                *(float2*)(C + (long)row1 * N + col) =
                    make_float2(acc[mi][ni].z + bv.x, acc[mi][ni].w + bv.y);
        }
    }
}

// ---------------------------------------------------------------------------
// Sampling kernel: warp = (b, h, 2 queries); parity-aligned corner reads.
// ---------------------------------------------------------------------------
__global__ __launch_bounds__(256) void sample_kernel(
    const float* __restrict__ ref_points, __half* __restrict__ xout)
{
    __shared__ uint2 s_iw[8][2][16][4];

    const int lane = threadIdx.x & 31;
    const int warp = threadIdx.x >> 5;
    const int bh   = blockIdx.y;
    const int b    = bh >> 3;
    const int h    = bh & 7;
    const int qbase = blockIdx.x * 16 + warp * 2;

    {
        const int qi = lane >> 4;
        const int sm = lane & 15;
        const int qv = qbase + qi;
        const int qc = min(qv, LEN_Q_ - 1);
        const long bq = (long)b * LEN_Q_ + qc;

        float logit = g_aw[bq * 128 + h * 16 + sm];
        float mx = logit;
#pragma unroll
        for (int s = 8; s; s >>= 1)
            mx = fmaxf(mx, __shfl_xor_sync(0xffffffffu, mx, s));
        float e = __expf(logit - mx);
        float ssum = e;
#pragma unroll
        for (int s = 8; s; s >>= 1)
            ssum += __shfl_xor_sync(0xffffffffu, ssum, s);

        const int l  = sm >> 2;
        const int w  = c_lw[l];
        const int hh = c_lh[l];

        float2 off = ((const float2*)(g_off + bq * 256 + h * 32))[sm];
        float2 rp  = ((const float2*)(ref_points + bq * 8))[l];

        float px = fmaf(rp.x, (float)w,  off.x) - 0.5f;
        float py = fmaf(rp.y, (float)hh, off.y) - 0.5f;

        int x0 = (int)floorf(px);
        int y0 = (int)floorf(py);
        float dx = px - (float)x0;
        float dy = py - (float)y0;

        int xb = min(max(x0, 0), w - 2);
        int yb = min(max(y0, 0), hh - 2);

        float wxp0 = (xb == x0) ? (1.f - dx) : ((xb == x0 + 1) ? dx : 0.f);
        float wxp1 = (xb + 1 == x0) ? (1.f - dx) : ((xb == x0) ? dx : 0.f);
        float wyp0 = (yb == y0) ? (1.f - dy) : ((yb == y0 + 1) ? dy : 0.f);
        float wyp1 = (yb + 1 == y0) ? (1.f - dy) : ((yb == y0) ? dy : 0.f);

        const float aw = e / ssum;
        int base = c_start[l] + yb * w + xb;
        // pick copy so the (x, x+1) pixel pair starts 128B-aligned
        unsigned ab = (xb & 1) ? (unsigned)(VH_BYTES + (base - 1) * 64)
                               : (unsigned)(base * 64);
        unsigned rowstep = (unsigned)(w * 64);

        if (qv < LEN_Q_) {
            uint4 rec01, rec23;
            rec01.x = ab;
            rec01.y = __float_as_uint(aw * wyp0 * wxp0);
            rec01.z = ab + 64;
            rec01.w = __float_as_uint(aw * wyp0 * wxp1);
            rec23.x = ab + rowstep;
            rec23.y = __float_as_uint(aw * wyp1 * wxp0);
            rec23.z = ab + rowstep + 64;
            rec23.w = __float_as_uint(aw * wyp1 * wxp1);
            *(uint4*)&s_iw[warp][qi][sm][0] = rec01;
            *(uint4*)&s_iw[warp][qi][sm][2] = rec23;
        }
    }
    __syncwarp();

    const int c = lane >> 3;
    const char* vbl = (const char*)g_vh + ((long)(b * 8 + h) * LEN_V_) * 64
                      + (lane & 7) * 8;

#pragma unroll
    for (int qi = 0; qi < 2; qi++) {
        const int qv = qbase + qi;
        if (qv >= LEN_Q_) break;
        float4 acc = make_float4(0.f, 0.f, 0.f, 0.f);
#pragma unroll
        for (int s = 0; s < 16; s++) {
            uint2 iw = s_iw[warp][qi][s][c];
            float wgt = __uint_as_float(iw.y);
            uint2 raw = *(const uint2*)(vbl + iw.x);
            float2 p0 = __half22float2(*(const __half2*)&raw.x);
            float2 p1 = __half22float2(*(const __half2*)&raw.y);
            acc.x = fmaf(wgt, p0.x, acc.x);
            acc.y = fmaf(wgt, p0.y, acc.y);
            acc.z = fmaf(wgt, p1.x, acc.z);
            acc.w = fmaf(wgt, p1.y, acc.w);
        }
#pragma unroll
        for (int d = 8; d < 32; d <<= 1) {
            acc.x += __shfl_xor_sync(0xffffffffu, acc.x, d);
            acc.y += __shfl_xor_sync(0xffffffffu, acc.y, d);
            acc.z += __shfl_xor_sync(0xffffffffu, acc.z, d);
            acc.w += __shfl_xor_sync(0xffffffffu, acc.w, d);
        }
        if (lane < 8) {
            long bq = (long)b * LEN_Q_ + qv;
            uint2 pk;
            pk.x = cvt_h2_rn(acc.x, acc.y);
            pk.y = cvt_h2_rn(acc.z, acc.w);
            *(uint2*)(xout + bq * 256 + h * 32 + lane * 4) = pk;
        }
    }
}

// ---------------------------------------------------------------------------
// launch
// ---------------------------------------------------------------------------
extern "C" void kernel_launch(void* const* d_in, const int* in_sizes, int n_in,
                              void* d_out, int out_size)
{
    (void)in_sizes; (void)n_in; (void)out_size;
    const float* query = (const float*)d_in[0];
    const float* refp  = (const float*)d_in[1];
    const float* value = (const float*)d_in[2];
    const float* vpk   = (const float*)d_in[4];
    const float* vpb   = (const float*)d_in[5];
    const float* sok   = (const float*)d_in[6];
    const float* sob   = (const float*)d_in[7];
    const float* ak    = (const float*)d_in[8];
    const float* ab    = (const float*)d_in[9];
    const float* okern = (const float*)d_in[10];
    const float* obias = (const float*)d_in[11];
    float* out = (float*)d_out;

    float*  go  = nullptr; cudaGetSymbolAddress((void**)&go,  g_off);
    float*  ga  = nullptr; cudaGetSymbolAddress((void**)&ga,  g_aw);
    __half* gxh = nullptr; cudaGetSymbolAddress((void**)&gxh, g_xh);
    __half* wh  = nullptr; cudaGetSymbolAddress((void**)&wh,  g_wh);
    float* bcat = nullptr; cudaGetSymbolAddress((void**)&bcat, g_biascat);

    const int M = MROWS_;
    dim3 blk(256);
    const int myb = (M + 127) / 128;   // 287

    prep_weights_kernel<<<dim3(256, 4), blk>>>(vpk, sok, ak, okern, sob, ab);

    const long SLOT = 384 * (long)KDIM_;
    // 1) value projection -> dual head-major fp16 cache
    mma_gemm_f16_kernel<<<dim3(2, myb), blk>>>(value, wh + 0 * SLOT, vpb,
                                               nullptr, nullptr, M, 256, 0, 0, 1);
    // 2+3) fused query GEMM -> g_off / g_aw (fp32)
    mma_gemm_f16_kernel<<<dim3(3, myb), blk>>>(query, wh + 1 * SLOT, bcat,
                                               go, ga, M, 256, 256, 128, 0);
    // 4) sampling -> g_xh (fp16)
    dim3 sgrid((LEN_Q_ + 15) / 16, BS_ * HEADS_);
    sample_kernel<<<sgrid, blk>>>(refp, gxh);
    // 5) output projection (fp16 x fp16) -> d_out
    mma_gemm_f16f16_kernel<<<dim3(2, myb), blk>>>(gxh, wh + 2 * SLOT, obias,
                                                  out, M, 256);
}

// round 16
// speedup vs baseline: 1.0657x; 1.0657x over previous
#include <cuda_runtime.h>
#include <cuda_bf16.h>
#include <cuda_fp16.h>
#include <cstdint>

// ---------------------------------------------------------------------------
// MultiScaleDeformableAttention
//   R16: R10 GEMMs (single-buffer fp16 HMMA) + dual parity value cache.
//        Sample Phase B: LDG.128, 2 samples/iter, HFMA2 accumulation,
//        half2 xor-reduction, direct fp16 STG.128 (no converts).
// ---------------------------------------------------------------------------

#define BS_       2
#define HEADS_    8
#define LEVELS_   4
#define LEN_V_    18360
#define LEN_Q_    18360
#define MROWS_    (BS_ * LEN_Q_)   // 36720
#define KDIM_     256
#define VH_HALVES (BS_ * HEADS_ * LEN_V_ * 32)
#define VH_BYTES  (VH_HALVES * 2)

__device__ __constant__ int c_lh[LEVELS_]    = {96, 48, 24, 12};
__device__ __constant__ int c_lw[LEVELS_]    = {144, 72, 36, 18};
__device__ __constant__ int c_start[LEVELS_] = {0, 13824, 17280, 18144};

// scratch
__device__ __half g_vh [2 * VH_HALVES + 64];   // copyA | copyB (shift -1 px)
__device__ float  g_off[BS_ * LEN_Q_ * 256];
__device__ float  g_aw [BS_ * LEN_Q_ * 128 + 2048];
__device__ __half g_xh [MROWS_ * 256];

// fp16 weights [N][K]: slot0 vpk(256), slot1 sok|ak(384), slot2 okern(256)
__device__ __half g_wh [3][384 * KDIM_];
__device__ float  g_biascat[384];

// ---------------------------------------------------------------------------
// helpers
// ---------------------------------------------------------------------------
__device__ __forceinline__ uint32_t cvt_h2_rn(float lo, float hi) {
    uint32_t r;
    asm("cvt.rn.f16x2.f32 %0, %1, %2;" : "=r"(r) : "f"(hi), "f"(lo));
    return r;
}
__device__ __forceinline__ void ldsm4(uint32_t& r0, uint32_t& r1, uint32_t& r2,
                                      uint32_t& r3, uint32_t addr) {
    asm volatile("ldmatrix.sync.aligned.m8n8.x4.shared.b16 {%0,%1,%2,%3}, [%4];"
                 : "=r"(r0), "=r"(r1), "=r"(r2), "=r"(r3) : "r"(addr));
}
__device__ __forceinline__ void mma_f16(float4& d, const uint32_t a[4],
                                        const uint32_t b[2]) {
    asm volatile(
        "mma.sync.aligned.m16n8k16.row.col.f32.f16.f16.f32 "
        "{%0,%1,%2,%3}, {%4,%5,%6,%7}, {%8,%9}, {%0,%1,%2,%3};"
        : "+f"(d.x), "+f"(d.y), "+f"(d.z), "+f"(d.w)
        : "r"(a[0]), "r"(a[1]), "r"(a[2]), "r"(a[3]), "r"(b[0]), "r"(b[1]));
}
__device__ __forceinline__ uint32_t hfma2_u(uint32_t w, uint32_t v, uint32_t c) {
    __half2 r = __hfma2(*(__half2*)&w, *(__half2*)&v, *(__half2*)&c);
    return *(uint32_t*)&r;
}
__device__ __forceinline__ uint32_t hadd2_sh(uint32_t a, int d) {
    uint32_t o = __shfl_xor_sync(0xffffffffu, a, d);
    __half2 r = __hadd2(*(__half2*)&a, *(__half2*)&o);
    return *(uint32_t*)&r;
}

// ---------------------------------------------------------------------------
// weight prep (one launch, 4 jobs on blockIdx.y) — all fp16
// ---------------------------------------------------------------------------
__global__ __launch_bounds__(256) void prep_weights_kernel(
    const float* __restrict__ vpk, const float* __restrict__ sok,
    const float* __restrict__ ak,  const float* __restrict__ okern,
    const float* __restrict__ sob, const float* __restrict__ ab)
{
    const int job = blockIdx.y;
    const float* src;
    int N, rowoff, slot;
    switch (job) {
        case 0:  src = vpk;   N = 256; slot = 0; rowoff = 0;   break;
        case 1:  src = sok;   N = 256; slot = 1; rowoff = 0;   break;
        case 2:  src = ak;    N = 128; slot = 1; rowoff = 256; break;
        default: src = okern; N = 256; slot = 2; rowoff = 0;   break;
    }
    int idx = blockIdx.x * 256 + threadIdx.x;
    if (idx < N * 256) {
        int n = idx >> 8;
        int k = idx & 255;
        g_wh[slot][(rowoff + n) * 256 + k] = __float2half_rn(src[k * N + n]);
    }
    if (blockIdx.x == 0) {
        if (job == 1 && threadIdx.x < 256) g_biascat[threadIdx.x] = sob[threadIdx.x];
        if (job == 2 && threadIdx.x < 128) g_biascat[256 + threadIdx.x] = ab[threadIdx.x];
    }
}

// ---------------------------------------------------------------------------
// fp16 GEMM, fp32 A input (R10 single-buffer)
// out_mode 0: fp32 dual output   out_mode 1: fp16 head-major value cache x2
// ---------------------------------------------------------------------------
__global__ __launch_bounds__(256) void mma_gemm_f16_kernel(
    const float* __restrict__ A, const __half* __restrict__ W,
    const float* __restrict__ bias,
    float* __restrict__ C0, float* __restrict__ C1,
    int M, int N0, int ld0, int ld1, int out_mode)
{
    __shared__ uint32_t sA[128 * 16];
    __shared__ uint32_t sB[128 * 16];

    const int tid    = threadIdx.x;
    const int lane   = tid & 31;
    const int wid    = tid >> 5;
    const int warp_m = wid & 1;
    const int warp_n = wid >> 1;
    const int bm     = blockIdx.y * 128;
    const int bn     = blockIdx.x * 128;

    const int lrow  = tid >> 1;
    const int lhalf = tid & 1;
    const int lsw   = (tid >> 2) & 3;
    const bool arow_ok = (bm + lrow) < M;
    const float*  aptr = A + (long)(bm + lrow) * 256 + lhalf * 16;
    const __half* wptr = W + (long)(bn + lrow) * 256 + lhalf * 16;
    const int soff0 = lrow * 16 + (((lhalf * 2 + 0) ^ lsw) << 2);
    const int soff1 = lrow * 16 + (((lhalf * 2 + 1) ^ lsw) << 2);

    const int l16 = lane & 15;
    const int hi4 = lane >> 4;
    const int fsw = (l16 >> 1) & 3;
    const uint32_t bA = (uint32_t)__cvta_generic_to_shared(sA);
    const uint32_t bB = (uint32_t)__cvta_generic_to_shared(sB);
    const uint32_t rA = (uint32_t)(warp_m * 64 + l16) * 64;
    const uint32_t rB = (uint32_t)(warp_n * 32 + l16) * 64;
    uint32_t coff[2];
    coff[0] = (uint32_t)(((0 * 2 + hi4) ^ fsw) * 16);
    coff[1] = (uint32_t)(((1 * 2 + hi4) ^ fsw) * 16);

    float4 acc[4][4];
#pragma unroll
    for (int mi = 0; mi < 4; mi++)
#pragma unroll
        for (int ni = 0; ni < 4; ni++) acc[mi][ni] = make_float4(0.f, 0.f, 0.f, 0.f);

    float4 pa[4];
    uint4  pb[2];

    if (arow_ok) {
        pa[0] = *(const float4*)(aptr + 0);
        pa[1] = *(const float4*)(aptr + 4);
        pa[2] = *(const float4*)(aptr + 8);
        pa[3] = *(const float4*)(aptr + 12);
    } else {
        pa[0] = pa[1] = pa[2] = pa[3] = make_float4(0.f, 0.f, 0.f, 0.f);
    }
    pb[0] = ((const uint4*)wptr)[0];
    pb[1] = ((const uint4*)wptr)[1];

#pragma unroll 1
    for (int k0 = 0; k0 < 8; k0++) {
#pragma unroll
        for (int j = 0; j < 2; j++) {
            float4 a0 = pa[2 * j], a1 = pa[2 * j + 1];
            uint4 h;
            h.x = cvt_h2_rn(a0.x, a0.y);
            h.y = cvt_h2_rn(a0.z, a0.w);
            h.z = cvt_h2_rn(a1.x, a1.y);
            h.w = cvt_h2_rn(a1.z, a1.w);
            int off = (j == 0) ? soff0 : soff1;
            *(uint4*)&sA[off] = h;
            *(uint4*)&sB[off] = pb[j];
        }
        __syncthreads();

        if (k0 < 7) {
            const float* ap = aptr + (k0 + 1) * 32;
            if (arow_ok) {
                pa[0] = *(const float4*)(ap + 0);
                pa[1] = *(const float4*)(ap + 4);
                pa[2] = *(const float4*)(ap + 8);
                pa[3] = *(const float4*)(ap + 12);
            }
            const uint4* wp = (const uint4*)(wptr + (k0 + 1) * 32);
            pb[0] = wp[0];
            pb[1] = wp[1];
        }

#pragma unroll
        for (int ks = 0; ks < 2; ks++) {
            uint32_t a[4][4], b[4][2];
#pragma unroll
            for (int mi = 0; mi < 4; mi++) {
                uint32_t ad = rA + (uint32_t)(mi * 1024) + coff[ks];
                ldsm4(a[mi][0], a[mi][1], a[mi][2], a[mi][3], bA + ad);
            }
#pragma unroll
            for (int nip = 0; nip < 2; nip++) {
                uint32_t bd = rB + (uint32_t)(nip * 1024) + coff[ks];
                uint32_t t0, t1, t2, t3;
                ldsm4(t0, t1, t2, t3, bB + bd);
                b[2 * nip][0] = t0; b[2 * nip + 1][0] = t1;
                b[2 * nip][1] = t2; b[2 * nip + 1][1] = t3;
            }
#pragma unroll
            for (int mi = 0; mi < 4; mi++)
#pragma unroll
                for (int ni = 0; ni < 4; ni++)
                    mma_f16(acc[mi][ni], a[mi], b[ni]);
        }
        __syncthreads();
    }

    const int qrow = lane >> 2;
    const int qk   = lane & 3;
    __half* gvh = (__half*)g_vh;
#pragma unroll
    for (int mi = 0; mi < 4; mi++) {
#pragma unroll
        for (int ni = 0; ni < 4; ni++) {
            int col = bn + warp_n * 32 + ni * 8 + qk * 2;
            float2 bv = *(const float2*)(bias + col);
            int row0 = bm + warp_m * 64 + mi * 16 + qrow;
            int row1 = row0 + 8;
            float2 o0 = make_float2(acc[mi][ni].x + bv.x, acc[mi][ni].y + bv.y);
            float2 o1 = make_float2(acc[mi][ni].z + bv.x, acc[mi][ni].w + bv.y);
            if (out_mode == 1) {
                int h = col >> 5, d = col & 31;
#pragma unroll
                for (int rr = 0; rr < 2; rr++) {
                    int row = rr ? row1 : row0;
                    if (row < M) {
                        int b = row >= LEN_V_;
                        int v = row - b * LEN_V_;
                        long ib = (long)(b * 8 + h) * LEN_V_;
                        float2 ov = rr ? o1 : o0;
                        uint32_t pk = cvt_h2_rn(ov.x, ov.y);
                        *(uint32_t*)(gvh + (ib + v) * 32 + d) = pk;
                        if (v >= 1)
                            *(uint32_t*)(gvh + VH_HALVES + (ib + v - 1) * 32 + d) = pk;
                    }
                }
            } else {
                float* Cp; int ldc, cc;
                if (col < N0) { Cp = C0; ldc = ld0; cc = col; }
                else          { Cp = C1; ldc = ld1; cc = col - N0; }
                if (row0 < M) *(float2*)(Cp + (long)row0 * ldc + cc) = o0;
                if (row1 < M) *(float2*)(Cp + (long)row1 * ldc + cc) = o1;
            }
        }
    }
}

// ---------------------------------------------------------------------------
// fp16 GEMM, fp16 A input (out projection; R10 single-buffer)
// ---------------------------------------------------------------------------
__global__ __launch_bounds__(256) void mma_gemm_f16f16_kernel(
    const __half* __restrict__ A, const __half* __restrict__ W,
    const float* __restrict__ bias, float* __restrict__ C, int M, int N)
{
    __shared__ uint32_t sA[128 * 16];
    __shared__ uint32_t sB[128 * 16];

    const int tid    = threadIdx.x;
    const int lane   = tid & 31;
    const int wid    = tid >> 5;
    const int warp_m = wid & 1;
    const int warp_n = wid >> 1;
    const int bm     = blockIdx.y * 128;
    const int bn     = blockIdx.x * 128;

    const int lrow  = tid >> 1;
    const int lhalf = tid & 1;
    const int lsw   = (tid >> 2) & 3;
    const int arow  = min(bm + lrow, M - 1);
    const __half* aptr = A + (long)arow * 256 + lhalf * 16;
    const __half* wptr = W + (long)(bn + lrow) * 256 + lhalf * 16;
    const int soff0 = lrow * 16 + (((lhalf * 2 + 0) ^ lsw) << 2);
    const int soff1 = lrow * 16 + (((lhalf * 2 + 1) ^ lsw) << 2);

    const int l16 = lane & 15;
    const int hi4 = lane >> 4;
    const int fsw = (l16 >> 1) & 3;
    const uint32_t bA = (uint32_t)__cvta_generic_to_shared(sA);
    const uint32_t bB = (uint32_t)__cvta_generic_to_shared(sB);
    const uint32_t rA = (uint32_t)(warp_m * 64 + l16) * 64;
    const uint32_t rB = (uint32_t)(warp_n * 32 + l16) * 64;
    uint32_t coff[2];
    coff[0] = (uint32_t)(((0 * 2 + hi4) ^ fsw) * 16);
    coff[1] = (uint32_t)(((1 * 2 + hi4) ^ fsw) * 16);

    float4 acc[4][4];
#pragma unroll
    for (int mi = 0; mi < 4; mi++)
#pragma unroll
        for (int ni = 0; ni < 4; ni++) acc[mi][ni] = make_float4(0.f, 0.f, 0.f, 0.f);

    uint4 pa[2], pb[2];
    pa[0] = ((const uint4*)aptr)[0];
    pa[1] = ((const uint4*)aptr)[1];
    pb[0] = ((const uint4*)wptr)[0];
    pb[1] = ((const uint4*)wptr)[1];

#pragma unroll 1
    for (int k0 = 0; k0 < 8; k0++) {
        *(uint4*)&sA[soff0] = pa[0];
        *(uint4*)&sA[soff1] = pa[1];
        *(uint4*)&sB[soff0] = pb[0];
        *(uint4*)&sB[soff1] = pb[1];
        __syncthreads();

        if (k0 < 7) {
            const uint4* ap = (const uint4*)(aptr + (k0 + 1) * 32);
            const uint4* wp = (const uint4*)(wptr + (k0 + 1) * 32);
            pa[0] = ap[0]; pa[1] = ap[1];
            pb[0] = wp[0]; pb[1] = wp[1];
        }

#pragma unroll
        for (int ks = 0; ks < 2; ks++) {
            uint32_t a[4][4], b[4][2];
#pragma unroll
            for (int mi = 0; mi < 4; mi++) {
                uint32_t ad = rA + (uint32_t)(mi * 1024) + coff[ks];
                ldsm4(a[mi][0], a[mi][1], a[mi][2], a[mi][3], bA + ad);
            }
#pragma unroll
            for (int nip = 0; nip < 2; nip++) {
                uint32_t bd = rB + (uint32_t)(nip * 1024) + coff[ks];
                uint32_t t0, t1, t2, t3;
                ldsm4(t0, t1, t2, t3, bB + bd);
                b[2 * nip][0] = t0; b[2 * nip + 1][0] = t1;
                b[2 * nip][1] = t2; b[2 * nip + 1][1] = t3;
            }
#pragma unroll
            for (int mi = 0; mi < 4; mi++)
#pragma unroll
                for (int ni = 0; ni < 4; ni++)
                    mma_f16(acc[mi][ni], a[mi], b[ni]);
        }
        __syncthreads();
    }

    const int qrow = lane >> 2;
    const int qk   = lane & 3;
#pragma unroll
    for (int mi = 0; mi < 4; mi++) {
#pragma unroll
        for (int ni = 0; ni < 4; ni++) {
            int col = bn + warp_n * 32 + ni * 8 + qk * 2;
            float2 bv = *(const float2*)(bias + col);
            int row0 = bm + warp_m * 64 + mi * 16 + qrow;
            int row1 = row0 + 8;
            if (row0 < M)
                *(float2*)(C + (long)row0 * N + col) =
                    make_float2(acc[mi][ni].x + bv.x, acc[mi][ni].y + bv.y);
            if (row1 < M)
                *(float2*)(C + (long)row1 * N + col) =
                    make_float2(acc[mi][ni].z + bv.x, acc[mi][ni].w + bv.y);
        }
    }
}

// ---------------------------------------------------------------------------
// Sampling kernel R16: warp = (b, h, 2 queries).
//   Phase A: per-sample per-corner records {aligned addr, dup-half2 weight}.
//   Phase B: lane = s(1) y(1) xh(1) u(2); per iter handles 2 samples with one
//   LDG.128 per lane + 4 HFMA2. half2 xor-reduction, STG.128, no converts.
// ---------------------------------------------------------------------------
__global__ __launch_bounds__(256) void sample_kernel(
    const float* __restrict__ ref_points, __half* __restrict__ xout)
{
    __shared__ uint2 s_iw[8][2][16][4];   // [warp][qi][sample][corner]

    const int lane = threadIdx.x & 31;
    const int warp = threadIdx.x >> 5;
    const int bh   = blockIdx.y;
    const int b    = bh >> 3;
    const int h    = bh & 7;
    const int qbase = blockIdx.x * 16 + warp * 2;

    // ---- Phase A: lane -> (qi = lane>>4, sm = lane&15) ----
    {
        const int qi = lane >> 4;
        const int sm = lane & 15;
        const int qv = qbase + qi;
        const int qc = min(qv, LEN_Q_ - 1);
        const long bq = (long)b * LEN_Q_ + qc;

        float logit = g_aw[bq * 128 + h * 16 + sm];
        float mx = logit;
#pragma unroll
        for (int s = 8; s; s >>= 1)
            mx = fmaxf(mx, __shfl_xor_sync(0xffffffffu, mx, s));
        float e = __expf(logit - mx);
        float ssum = e;
#pragma unroll
        for (int s = 8; s; s >>= 1)
            ssum += __shfl_xor_sync(0xffffffffu, ssum, s);

        const int l  = sm >> 2;
        const int w  = c_lw[l];
        const int hh = c_lh[l];

        float2 off = ((const float2*)(g_off + bq * 256 + h * 32))[sm];
        float2 rp  = ((const float2*)(ref_points + bq * 8))[l];

        float px = fmaf(rp.x, (float)w,  off.x) - 0.5f;
        float py = fmaf(rp.y, (float)hh, off.y) - 0.5f;

        int x0 = (int)floorf(px);
        int y0 = (int)floorf(py);
        float dx = px - (float)x0;
        float dy = py - (float)y0;

        int xb = min(max(x0, 0), w - 2);
        int yb = min(max(y0, 0), hh - 2);

        float wxp0 = (xb == x0) ? (1.f - dx) : ((xb == x0 + 1) ? dx : 0.f);
        float wxp1 = (xb + 1 == x0) ? (1.f - dx) : ((xb == x0) ? dx : 0.f);
        float wyp0 = (yb == y0) ? (1.f - dy) : ((yb == y0 + 1) ? dy : 0.f);
        float wyp1 = (yb + 1 == y0) ? (1.f - dy) : ((yb == y0) ? dy : 0.f);

        const float aw = e / ssum;
        int base = c_start[l] + yb * w + xb;
        // pick copy so the (x, x+1) pixel pair is one 128B-aligned block
        unsigned ab = (xb & 1) ? (unsigned)(VH_BYTES + (base - 1) * 64)
                               : (unsigned)(base * 64);
        unsigned rowstep = (unsigned)(w * 64);

        if (qv < LEN_Q_) {
            float w00 = aw * wyp0 * wxp0, w01 = aw * wyp0 * wxp1;
            float w10 = aw * wyp1 * wxp0, w11 = aw * wyp1 * wxp1;
            uint4 rec01, rec23;
            rec01.x = ab;
            rec01.y = cvt_h2_rn(w00, w00);
            rec01.z = ab + 64;
            rec01.w = cvt_h2_rn(w01, w01);
            rec23.x = ab + rowstep;
            rec23.y = cvt_h2_rn(w10, w10);
            rec23.z = ab + rowstep + 64;
            rec23.w = cvt_h2_rn(w11, w11);
            *(uint4*)&s_iw[warp][qi][sm][0] = rec01;
            *(uint4*)&s_iw[warp][qi][sm][2] = rec23;
        }
    }
    __syncwarp();

    // ---- Phase B: lane = s(bit4) y(bit3) xh(bit2) u(bits0-1) ----
    const int sbit   = lane >> 4;          // sample parity within pair
    const int corner = (lane >> 2) & 3;    // y*2 + xh, matches record order
    const unsigned uoff = (unsigned)((lane & 3) * 16);
    const char* vbase = (const char*)g_vh + ((long)(b * 8 + h) * LEN_V_) * 64;

#pragma unroll
    for (int qi = 0; qi < 2; qi++) {
        const int qv = qbase + qi;
        if (qv >= LEN_Q_) break;
        uint32_t a0 = 0, a1 = 0, a2 = 0, a3 = 0;   // half2 accumulators
#pragma unroll
        for (int sp = 0; sp < 8; sp++) {
            uint2 rec = s_iw[warp][qi][sp * 2 + sbit][corner];
            uint4 raw = *(const uint4*)(vbase + rec.x + uoff);   // 8 fp16
            a0 = hfma2_u(rec.y, raw.x, a0);
            a1 = hfma2_u(rec.y, raw.y, a1);
            a2 = hfma2_u(rec.y, raw.z, a2);
            a3 = hfma2_u(rec.y, raw.w, a3);
        }
        // reduce over bits 2 (xh), 3 (y), 4 (s)
#pragma unroll
        for (int d = 4; d < 32; d <<= 1) {
            a0 = hadd2_sh(a0, d);
            a1 = hadd2_sh(a1, d);
            a2 = hadd2_sh(a2, d);
            a3 = hadd2_sh(a3, d);
        }
        if (lane < 4) {
            long bq = (long)b * LEN_Q_ + qv;
            *(uint4*)(xout + bq * 256 + h * 32 + lane * 8) =
                make_uint4(a0, a1, a2, a3);
        }
    }
}

// ---------------------------------------------------------------------------
// launch
// ---------------------------------------------------------------------------
extern "C" void kernel_launch(void* const* d_in, const int* in_sizes, int n_in,
                              void* d_out, int out_size)
{
    (void)in_sizes; (void)n_in; (void)out_size;
    const float* query = (const float*)d_in[0];
    const float* refp  = (const float*)d_in[1];
    const float* value = (const float*)d_in[2];
    const float* vpk   = (const float*)d_in[4];
    const float* vpb   = (const float*)d_in[5];
    const float* sok   = (const float*)d_in[6];
    const float* sob   = (const float*)d_in[7];
    const float* ak    = (const float*)d_in[8];
    const float* ab    = (const float*)d_in[9];
    const float* okern = (const float*)d_in[10];
    const float* obias = (const float*)d_in[11];
    float* out = (float*)d_out;

    float*  go  = nullptr; cudaGetSymbolAddress((void**)&go,  g_off);
    float*  ga  = nullptr; cudaGetSymbolAddress((void**)&ga,  g_aw);
    __half* gxh = nullptr; cudaGetSymbolAddress((void**)&gxh, g_xh);
    __half* wh  = nullptr; cudaGetSymbolAddress((void**)&wh,  g_wh);
    float* bcat = nullptr; cudaGetSymbolAddress((void**)&bcat, g_biascat);

    const int M = MROWS_;
    dim3 blk(256);
    const int myb = (M + 127) / 128;   // 287

    prep_weights_kernel<<<dim3(256, 4), blk>>>(vpk, sok, ak, okern, sob, ab);

    const long SLOT = 384 * (long)KDIM_;
    // 1) value projection -> dual head-major fp16 cache
    mma_gemm_f16_kernel<<<dim3(2, myb), blk>>>(value, wh + 0 * SLOT, vpb,
                                               nullptr, nullptr, M, 256, 0, 0, 1);
    // 2+3) fused query GEMM -> g_off / g_aw (fp32)
    mma_gemm_f16_kernel<<<dim3(3, myb), blk>>>(query, wh + 1 * SLOT, bcat,
                                               go, ga, M, 256, 256, 128, 0);
    // 4) sampling -> g_xh (fp16)
    dim3 sgrid((LEN_Q_ + 15) / 16, BS_ * HEADS_);
    sample_kernel<<<sgrid, blk>>>(refp, gxh);
    // 5) output projection (fp16 x fp16) -> d_out
    mma_gemm_f16f16_kernel<<<dim3(2, myb), blk>>>(gxh, wh + 2 * SLOT, obias,
                                                  out, M, 256);
}